// round 2
// baseline (speedup 1.0000x reference)
#include <cuda_runtime.h>
#include <math.h>

#define BB 32
#define TT 1024
#define II 512
#define HH 512
#define G4 2048      // 4*H
#define GRID_P 128   // persistent CTAs (<=148 -> co-resident, deadlock-free)

// ---------------- scratch (static device globals; no allocation) ----------------
__device__ float    g_xpre[(size_t)BB * TT * G4];   // [B][T][4H]  256 MB
__device__ float    g_hT[HH * BB];                  // h transposed [j][b]
__device__ unsigned g_bar_count;
__device__ unsigned g_bar_phase;

// ---------------- Kernel 0: init (reset barrier, h0 -> h_T) ----------------
__global__ void init_kernel(const float* __restrict__ h0, float* __restrict__ hT)
{
    int i = blockIdx.x * 256 + threadIdx.x;     // 16384 elems
    if (i < BB * HH) {
        int b = i >> 9;
        int j = i & 511;
        hT[j * BB + b] = h0[i];
    }
    if (i == 0) { g_bar_count = 0; g_bar_phase = 0; }
}

// ---------------- Kernel 1: x_pre = x @ [Wii|Wif|Wio|Wig] + bias ----------------
// Tiled FP32 SGEMM: 128x128 tile, K-step 8, 256 threads, 8x8 per thread.
// M = 32768 (B*T), N = 2048 (4 gates x 512), K = 512.
__global__ __launch_bounds__(256) void gemm_x_kernel(
    const float* __restrict__ X,
    const float* __restrict__ Wii, const float* __restrict__ Wif,
    const float* __restrict__ Wio, const float* __restrict__ Wig,
    const float* __restrict__ bi, const float* __restrict__ bf,
    const float* __restrict__ bo, const float* __restrict__ bg,
    float* __restrict__ xpre)
{
    const int mtile = blockIdx.x;          // 0..255
    const int gtile = blockIdx.y;          // 0..15
    const int gate  = gtile >> 2;
    const int j0    = (gtile & 3) * 128;

    const float* W    = (gate == 0) ? Wii : (gate == 1) ? Wif : (gate == 2) ? Wio : Wig;
    const float* bias = (gate == 0) ? bi  : (gate == 1) ? bf  : (gate == 2) ? bo  : bg;

    __shared__ float As[8][132];
    __shared__ float Bs[8][128];

    const int tid = threadIdx.x;
    const int tx = tid & 15;
    const int ty = tid >> 4;
    const int m0 = mtile * 128;

    const int a_row = tid >> 1;
    const int a_k   = (tid & 1) * 4;
    const int b_k = tid >> 5;
    const int b_n = (tid & 31) * 4;

    float acc[8][8];
#pragma unroll
    for (int i = 0; i < 8; i++)
#pragma unroll
        for (int j = 0; j < 8; j++) acc[i][j] = 0.0f;

    for (int k0 = 0; k0 < 512; k0 += 8) {
        float4 av = *(const float4*)(X + (size_t)(m0 + a_row) * 512 + k0 + a_k);
        As[a_k + 0][a_row] = av.x;
        As[a_k + 1][a_row] = av.y;
        As[a_k + 2][a_row] = av.z;
        As[a_k + 3][a_row] = av.w;
        float4 bv = *(const float4*)(W + (size_t)(k0 + b_k) * 512 + j0 + b_n);
        *(float4*)&Bs[b_k][b_n] = bv;
        __syncthreads();

#pragma unroll
        for (int kk = 0; kk < 8; kk++) {
            float ar[8], br[8];
            float4 a0 = *(const float4*)&As[kk][ty * 8];
            float4 a1 = *(const float4*)&As[kk][ty * 8 + 4];
            ar[0]=a0.x; ar[1]=a0.y; ar[2]=a0.z; ar[3]=a0.w;
            ar[4]=a1.x; ar[5]=a1.y; ar[6]=a1.z; ar[7]=a1.w;
            float4 b0 = *(const float4*)&Bs[kk][tx * 8];
            float4 b1 = *(const float4*)&Bs[kk][tx * 8 + 4];
            br[0]=b0.x; br[1]=b0.y; br[2]=b0.z; br[3]=b0.w;
            br[4]=b1.x; br[5]=b1.y; br[6]=b1.z; br[7]=b1.w;
#pragma unroll
            for (int i = 0; i < 8; i++)
#pragma unroll
                for (int j = 0; j < 8; j++)
                    acc[i][j] = fmaf(ar[i], br[j], acc[i][j]);
        }
        __syncthreads();
    }

#pragma unroll
    for (int i = 0; i < 8; i++) {
        const size_t m = (size_t)(m0 + ty * 8 + i);
        float* dst = xpre + m * G4 + gate * 512 + j0 + tx * 8;
        float4 o0, o1;
        o0.x = acc[i][0] + bias[j0 + tx * 8 + 0];
        o0.y = acc[i][1] + bias[j0 + tx * 8 + 1];
        o0.z = acc[i][2] + bias[j0 + tx * 8 + 2];
        o0.w = acc[i][3] + bias[j0 + tx * 8 + 3];
        o1.x = acc[i][4] + bias[j0 + tx * 8 + 4];
        o1.y = acc[i][5] + bias[j0 + tx * 8 + 5];
        o1.z = acc[i][6] + bias[j0 + tx * 8 + 6];
        o1.w = acc[i][7] + bias[j0 + tx * 8 + 7];
        *(float4*)dst       = o0;
        *(float4*)(dst + 4) = o1;
    }
}

// ---------------- Kernel 2: persistent recurrence ----------------
// 128 CTAs x 256 threads. CTA owns 4 h-columns jc..jc+3 (16 gate-cols).
// Weights for those 16 gate-cols live in SMEM for all 1024 steps.
// Per step: load h_T (coalesced), GEMM slice, gates, write h_T slice, grid barrier.
//
// Dynamic SMEM layout (floats):
//   sh_h  [512*32]   = 65536 B   h[k][b]
//   sh_w  [16*512]   = 32768 B   w[gc][k]
//   sh_ps [8*4*32]   =  4096 B   partial sums [warp][jj][b]
//   sh_xs [4*32*4]   =  2048 B   xpre staged [q][b][jj]
//   sh_c  [4*32]     =   512 B   cell state [jj][b]
//   sh_ho [32*4]     =   512 B   h output staging [b][jj]
#define SH_H  0
#define SH_W  (SH_H  + 512*32)
#define SH_PS (SH_W  + 16*512)
#define SH_XS (SH_PS + 8*4*32)
#define SH_C  (SH_XS + 4*32*4)
#define SH_HO (SH_C  + 4*32)
#define SH_TOTAL_FLOATS (SH_HO + 32*4)

extern __shared__ float smem_p[];

__global__ __launch_bounds__(256, 1) void lstm_persist_kernel(
    const float* __restrict__ xpre,
    const float* __restrict__ Whi, const float* __restrict__ Whf,
    const float* __restrict__ Who, const float* __restrict__ Whg,
    const float* __restrict__ c0,
    float* __restrict__ hT,
    float* __restrict__ out,
    int write_tail)
{
    float* sh_h  = smem_p + SH_H;
    float* sh_w  = smem_p + SH_W;
    float* sh_ps = smem_p + SH_PS;
    float* sh_xs = smem_p + SH_XS;
    float* sh_c  = smem_p + SH_C;
    float* sh_ho = smem_p + SH_HO;

    const int tid  = threadIdx.x;
    const int lane = tid & 31;
    const int w    = tid >> 5;
    const int jc   = blockIdx.x * 4;        // h-column base

    // ---- one-time: load weight slice (16 gate-cols x 512 k) ----
    for (int e = tid; e < 16 * 512; e += 256) {
        int gc = e >> 9;
        int k  = e & 511;
        int q  = gc >> 2;
        int jj = gc & 3;
        const float* Wq = (q == 0) ? Whi : (q == 1) ? Whf : (q == 2) ? Who : Whg;
        sh_w[gc * 512 + k] = Wq[(size_t)k * HH + jc + jj];
    }
    // ---- one-time: init cell state slice ----
    if (tid < 128) {
        int jj = tid >> 5;
        int b  = tid & 31;
        sh_c[jj * 32 + b] = c0[b * HH + jc + jj];
    }
    __syncthreads();

    const int q_gate = w & 3;     // gate this warp computes
    const int khalf  = w >> 2;    // k-split half
    const float* w0r = sh_w + (q_gate * 4 + 0) * 512;
    const float* w1r = sh_w + (q_gate * 4 + 1) * 512;
    const float* w2r = sh_w + (q_gate * 4 + 2) * 512;
    const float* w3r = sh_w + (q_gate * 4 + 3) * 512;
    const int kbeg = khalf * 256;

    for (int t = 0; t < TT; ++t) {
        // ---- stage h (coalesced) and xpre slice ----
        {
            const float4* src = (const float4*)hT;
            float4* dst = (float4*)sh_h;
#pragma unroll
            for (int i = 0; i < 16; i++)
                dst[tid + i * 256] = src[tid + i * 256];
        }
        if (tid < 128) {
            int b = tid >> 2;
            int q = tid & 3;
            float4 v = *(const float4*)(xpre + ((size_t)b * TT + t) * G4 + q * 512 + jc);
            *(float4*)(sh_xs + (q * 32 + b) * 4) = v;
        }
        __syncthreads();

        // ---- recurrent GEMM slice: acc[jj] = sum_k h[b][k] * w[gc][k] ----
        float acc0 = 0.f, acc1 = 0.f, acc2 = 0.f, acc3 = 0.f;
#pragma unroll 4
        for (int k = kbeg; k < kbeg + 256; k += 4) {
            float h0 = sh_h[(k + 0) * 32 + lane];
            float h1 = sh_h[(k + 1) * 32 + lane];
            float h2 = sh_h[(k + 2) * 32 + lane];
            float h3 = sh_h[(k + 3) * 32 + lane];
            float4 v0 = *(const float4*)(w0r + k);
            float4 v1 = *(const float4*)(w1r + k);
            float4 v2 = *(const float4*)(w2r + k);
            float4 v3 = *(const float4*)(w3r + k);
            acc0 = fmaf(h0, v0.x, fmaf(h1, v0.y, fmaf(h2, v0.z, fmaf(h3, v0.w, acc0))));
            acc1 = fmaf(h0, v1.x, fmaf(h1, v1.y, fmaf(h2, v1.z, fmaf(h3, v1.w, acc1))));
            acc2 = fmaf(h0, v2.x, fmaf(h1, v2.y, fmaf(h2, v2.z, fmaf(h3, v2.w, acc2))));
            acc3 = fmaf(h0, v3.x, fmaf(h1, v3.y, fmaf(h2, v3.z, fmaf(h3, v3.w, acc3))));
        }
        sh_ps[w * 128 + 0 * 32 + lane] = acc0;
        sh_ps[w * 128 + 1 * 32 + lane] = acc1;
        sh_ps[w * 128 + 2 * 32 + lane] = acc2;
        sh_ps[w * 128 + 3 * 32 + lane] = acc3;
        __syncthreads();

        // ---- gates + state update (128 threads: jj x b) ----
        if (tid < 128) {
            int jj = tid >> 5;
            int b  = tid & 31;
            float vi = sh_xs[(0 * 32 + b) * 4 + jj] + sh_ps[0 * 128 + jj * 32 + b] + sh_ps[4 * 128 + jj * 32 + b];
            float vf = sh_xs[(1 * 32 + b) * 4 + jj] + sh_ps[1 * 128 + jj * 32 + b] + sh_ps[5 * 128 + jj * 32 + b];
            float vo = sh_xs[(2 * 32 + b) * 4 + jj] + sh_ps[2 * 128 + jj * 32 + b] + sh_ps[6 * 128 + jj * 32 + b];
            float vg = sh_xs[(3 * 32 + b) * 4 + jj] + sh_ps[3 * 128 + jj * 32 + b] + sh_ps[7 * 128 + jj * 32 + b];
            float it = 1.0f / (1.0f + expf(-vi));
            float ft = 1.0f / (1.0f + expf(-vf));
            float ot = 1.0f / (1.0f + expf(-vo));
            float gt = tanhf(vg);
            float cn = ft * sh_c[jj * 32 + b] + it * gt;
            float hn = ot * tanhf(cn);
            sh_c[jj * 32 + b] = cn;
            sh_ho[b * 4 + jj] = hn;
            hT[(jc + jj) * BB + b] = hn;     // coalesced 128B per jj
        }
        __syncthreads();

        // ---- output write (float4 per batch) ----
        if (tid < 32) {
            int b = tid;
            *(float4*)(out + ((size_t)b * TT + t) * HH + jc) = *(float4*)(sh_ho + b * 4);
        }

        // ---- grid barrier ----
        if (tid == 0) {
            __threadfence();
            unsigned a = atomicAdd(&g_bar_count, 1u);
            if (a == (unsigned)(GRID_P - 1)) {
                g_bar_count = 0;
                __threadfence();
                *(volatile unsigned*)&g_bar_phase = (unsigned)(t + 1);
            } else {
                while (*(volatile unsigned*)&g_bar_phase <= (unsigned)t)
                    __nanosleep(64);
            }
            __threadfence();
        }
        __syncthreads();
    }

    // ---- final (h_t, c_t) tail ----
    if (write_tail && tid < 128) {
        int jj = tid >> 5;
        int b  = tid & 31;
        const size_t tail = (size_t)BB * TT * HH;
        out[tail + (size_t)b * HH + jc + jj]           = sh_ho[b * 4 + jj];
        out[tail + (size_t)BB * HH + (size_t)b * HH + jc + jj] = sh_c[jj * 32 + b];
    }
}

// ---------------- launch ----------------
extern "C" void kernel_launch(void* const* d_in, const int* in_sizes, int n_in,
                              void* d_out, int out_size) {
    const float* x   = (const float*)d_in[0];
    const float* h0  = (const float*)d_in[1];
    const float* c0  = (const float*)d_in[2];
    const float* Wii = (const float*)d_in[3];
    const float* Wif = (const float*)d_in[4];
    const float* Wio = (const float*)d_in[5];
    const float* Wig = (const float*)d_in[6];
    const float* Whi = (const float*)d_in[7];
    const float* Whf = (const float*)d_in[8];
    const float* Who = (const float*)d_in[9];
    const float* Whg = (const float*)d_in[10];
    const float* bi  = (const float*)d_in[11];
    const float* bf_ = (const float*)d_in[12];
    const float* bo  = (const float*)d_in[13];
    const float* bg  = (const float*)d_in[14];
    float* out = (float*)d_out;

    float *xpre, *hT;
    cudaGetSymbolAddress((void**)&xpre, g_xpre);
    cudaGetSymbolAddress((void**)&hT,   g_hT);

    const size_t smem_bytes = SH_TOTAL_FLOATS * sizeof(float);
    static int configured = 0;
    if (!configured) {
        cudaFuncSetAttribute(lstm_persist_kernel,
                             cudaFuncAttributeMaxDynamicSharedMemorySize,
                             (int)smem_bytes);
        configured = 1;
    }

    const long long tail = (long long)BB * TT * HH;
    const int write_tail = ((long long)out_size >= tail + 2LL * BB * HH) ? 1 : 0;

    init_kernel<<<64, 256>>>(h0, hT);
    gemm_x_kernel<<<dim3(256, 16), 256>>>(x, Wii, Wif, Wio, Wig, bi, bf_, bo, bg, xpre);
    lstm_persist_kernel<<<GRID_P, 256, smem_bytes>>>(
        xpre, Whi, Whf, Who, Whg, c0, hT, out, write_tail);
}